// round 3
// baseline (speedup 1.0000x reference)
#include <cuda_runtime.h>
#include <cstdint>
#include <cfloat>

#define NDOMS   262144
#define NPULSES 4194304
#define EMBED   64

// ---- static scratch (no allocs allowed) ----
__device__ int   g_count [NDOMS];
__device__ int   g_offset[NDOMS];
__device__ int   g_cursor[NDOMS];
__device__ int   g_perm  [NPULSES];
__device__ int   g_bsum  [256];
__device__ int   g_is64;
__device__ float g_wt    [128 * 64];              // W transposed: [k][j]
__device__ float g_concat[(size_t)NDOMS * 128];   // [NDOMS][128] mean|max

// ---------------------------------------------------------------- idx dtype probe
// int64 little-endian values < 2^31  =>  odd 32-bit words are all zero.
__global__ void k_detect(const unsigned int* __restrict__ idx32) {
    int is64 = 1;
    for (int i = 0; i < 128; i++)
        if (idx32[2 * i + 1] != 0u) { is64 = 0; break; }
    g_is64 = is64;
}

__device__ __forceinline__ int load_idx(const void* __restrict__ idx, int i) {
    if (g_is64) return (int)((const long long*)idx)[i];
    return ((const int*)idx)[i];
}

// ---------------------------------------------------------------- zero counts
__global__ void k_zero() {
    int i = blockIdx.x * 1024 + threadIdx.x;
    g_count[i] = 0;
}

// ---------------------------------------------------------------- W transpose
__global__ void k_wt(const float* __restrict__ W) {
    int s = blockIdx.x * 256 + threadIdx.x;      // 8192 threads
    int j = s >> 7, k = s & 127;
    g_wt[k * 64 + j] = W[s];                     // W[j][k] -> g_wt[k][j]
}

// ---------------------------------------------------------------- histogram
__global__ void k_hist(const void* __restrict__ idx, int n) {
    int i = blockIdx.x * 256 + threadIdx.x;
    if (i < n) atomicAdd(&g_count[load_idx(idx, i)], 1);
}

// ---------------------------------------------------------------- scan (3 phases)
__global__ void k_scan1() {
    __shared__ int sh[1024];
    int t = threadIdx.x;
    int i = blockIdx.x * 1024 + t;
    int v = g_count[i];
    sh[t] = v;
    __syncthreads();
    for (int off = 1; off < 1024; off <<= 1) {
        int add = (t >= off) ? sh[t - off] : 0;
        __syncthreads();
        sh[t] += add;
        __syncthreads();
    }
    g_offset[i] = sh[t] - v;                 // exclusive within block
    if (t == 1023) g_bsum[blockIdx.x] = sh[t];
}

__global__ void k_scan2() {
    __shared__ int sh[256];
    int t = threadIdx.x;
    int v = g_bsum[t];
    sh[t] = v;
    __syncthreads();
    for (int off = 1; off < 256; off <<= 1) {
        int add = (t >= off) ? sh[t - off] : 0;
        __syncthreads();
        sh[t] += add;
        __syncthreads();
    }
    g_bsum[t] = sh[t] - v;                   // exclusive block sums
}

__global__ void k_scan3() {
    int t = threadIdx.x;
    int i = blockIdx.x * 1024 + t;
    int o = g_offset[i] + g_bsum[blockIdx.x];
    g_offset[i] = o;
    g_cursor[i] = o;
}

// ---------------------------------------------------------------- scatter pulse ids
__global__ void k_scatter(const void* __restrict__ idx, int n) {
    int i = blockIdx.x * 256 + threadIdx.x;
    if (i < n) {
        int d   = load_idx(idx, i);
        int pos = atomicAdd(&g_cursor[d], 1);
        g_perm[pos] = i;
    }
}

// ---------------------------------------------------------------- pool: warp per DOM
// lane L owns dims {2L, 2L+1}; row read = 32 lanes x float2 = 256B coalesced.
__global__ void __launch_bounds__(256) k_pool(const float* __restrict__ emb) {
    int gw   = (blockIdx.x * blockDim.x + threadIdx.x) >> 5;   // global warp = dom
    int lane = threadIdx.x & 31;
    if (gw >= NDOMS) return;

    int start = g_offset[gw];
    int cnt   = g_count[gw];

    const float2* e2 = (const float2*)emb;
    float sx = 0.f, sy = 0.f;
    float mx = -FLT_MAX, my = -FLT_MAX;

    int p = (cnt > 0) ? g_perm[start] : 0;
    for (int i = 0; i < cnt; i++) {
        int pn = (i + 1 < cnt) ? g_perm[start + i + 1] : 0;   // prefetch next id
        float2 v = e2[(size_t)p * 32 + lane];
        sx += v.x; sy += v.y;
        mx = fmaxf(mx, v.x); my = fmaxf(my, v.y);
        p = pn;
    }

    float inv = 1.0f / (float)(cnt > 0 ? cnt : 1);
    if (cnt == 0) { mx = 0.f; my = 0.f; }     // empty segment: -inf -> 0

    float2* crow = (float2*)(g_concat + (size_t)gw * 128);
    crow[lane]      = make_float2(sx * inv, sy * inv);   // mean  -> cols [0,64)
    crow[32 + lane] = make_float2(mx, my);               // max   -> cols [64,128)
}

// ---------------------------------------------------------------- projection GEMM
// C[262144,64] = A[262144,128] @ Wt(128,64) + bias
// block: 32 dom-rows, full K=128, 128 threads, 4x4 micro-tile per thread.
// dyn smem = 16KB (As) + 32KB (Bs) = 49152B (== 48KB default cap, no opt-in)
__global__ void __launch_bounds__(128) k_gemm(const float* __restrict__ bias,
                                              float* __restrict__ out) {
    extern __shared__ float sm[];
    float* As = sm;                 // [32][128]
    float* Bs = sm + 32 * 128;      // [128][64]

    int tid  = threadIdx.x;
    int dom0 = blockIdx.x * 32;

    // load A tile (32 x 128) as float4: 1024 float4, 8 per thread
    const float4* A4 = (const float4*)(g_concat + (size_t)dom0 * 128);
    float4* As4 = (float4*)As;
    #pragma unroll
    for (int i = 0; i < 8; i++) {
        int s = tid + i * 128;
        As4[s] = A4[s];
    }
    // load pre-transposed W (128x64) as float4: 2048 float4, 16 per thread
    const float4* Wt4 = (const float4*)g_wt;
    float4* Bs4 = (float4*)Bs;
    #pragma unroll
    for (int i = 0; i < 16; i++) {
        int s = tid + i * 128;
        Bs4[s] = Wt4[s];
    }
    __syncthreads();

    int tj = tid & 15, tm = tid >> 4;
    int m0 = tm * 4, j0 = tj * 4;

    float c[4][4];
    #pragma unroll
    for (int i = 0; i < 4; i++)
        #pragma unroll
        for (int j = 0; j < 4; j++) c[i][j] = 0.f;

    #pragma unroll 8
    for (int k = 0; k < 128; k++) {
        float a0 = As[(m0 + 0) * 128 + k];
        float a1 = As[(m0 + 1) * 128 + k];
        float a2 = As[(m0 + 2) * 128 + k];
        float a3 = As[(m0 + 3) * 128 + k];
        float4 bb = *(const float4*)&Bs[k * 64 + j0];
        c[0][0] = fmaf(a0, bb.x, c[0][0]); c[0][1] = fmaf(a0, bb.y, c[0][1]);
        c[0][2] = fmaf(a0, bb.z, c[0][2]); c[0][3] = fmaf(a0, bb.w, c[0][3]);
        c[1][0] = fmaf(a1, bb.x, c[1][0]); c[1][1] = fmaf(a1, bb.y, c[1][1]);
        c[1][2] = fmaf(a1, bb.z, c[1][2]); c[1][3] = fmaf(a1, bb.w, c[1][3]);
        c[2][0] = fmaf(a2, bb.x, c[2][0]); c[2][1] = fmaf(a2, bb.y, c[2][1]);
        c[2][2] = fmaf(a2, bb.z, c[2][2]); c[2][3] = fmaf(a2, bb.w, c[2][3]);
        c[3][0] = fmaf(a3, bb.x, c[3][0]); c[3][1] = fmaf(a3, bb.y, c[3][1]);
        c[3][2] = fmaf(a3, bb.z, c[3][2]); c[3][3] = fmaf(a3, bb.w, c[3][3]);
    }

    float4 bb = *(const float4*)&bias[j0];
    #pragma unroll
    for (int i = 0; i < 4; i++) {
        float4 r;
        r.x = c[i][0] + bb.x; r.y = c[i][1] + bb.y;
        r.z = c[i][2] + bb.z; r.w = c[i][3] + bb.w;
        *(float4*)&out[(size_t)(dom0 + m0 + i) * 64 + j0] = r;
    }
}

// ---------------------------------------------------------------- launch
extern "C" void kernel_launch(void* const* d_in, const int* in_sizes, int n_in,
                              void* d_out, int out_size) {
    // identify inputs by size: accept element counts OR byte counts
    const float* emb = nullptr;
    const void*  idx = nullptr;
    const float* W   = nullptr;
    const float* b   = nullptr;
    for (int i = 0; i < n_in; i++) {
        long long sz = in_sizes[i];
        if (sz == 268435456LL || sz == 1073741824LL)           emb = (const float*)d_in[i];
        else if (sz == 4194304LL || sz == 33554432LL
                                 || sz == 16777216LL)          idx = d_in[i];
        else if (sz == 8192LL || sz == 32768LL)                W   = (const float*)d_in[i];
        else if (sz == 64LL  || sz == 256LL)                   b   = (const float*)d_in[i];
    }
    // positional fallback
    if (!emb || !idx || !W || !b) {
        emb = (const float*)d_in[0];
        idx = d_in[1];
        if (n_in >= 5) { W = (const float*)d_in[3]; b = (const float*)d_in[4]; }
        else           { W = (const float*)d_in[2]; b = (const float*)d_in[3]; }
    }
    float* out = (float*)d_out;
    const int n = NPULSES;

    k_detect <<<1, 1>>>((const unsigned int*)idx);
    k_zero   <<<NDOMS / 1024, 1024>>>();
    k_wt     <<<32, 256>>>(W);
    k_hist   <<<(n + 255) / 256, 256>>>(idx, n);
    k_scan1  <<<256, 1024>>>();
    k_scan2  <<<1, 256>>>();
    k_scan3  <<<256, 1024>>>();
    k_scatter<<<(n + 255) / 256, 256>>>(idx, n);
    k_pool   <<<NDOMS / 8, 256>>>(emb);
    k_gemm   <<<NDOMS / 32, 128, 49152>>>(b, out);
}

// round 4
// speedup vs baseline: 1.0636x; 1.0636x over previous
#include <cuda_runtime.h>
#include <cstdint>
#include <cfloat>

#define NDOMS   262144
#define NPULSES 4194304
#define EMBED   64

// ---- static scratch (no allocs allowed) ----
__device__ int   g_count [NDOMS];
__device__ int   g_offset[NDOMS];
__device__ int   g_cursor[NDOMS];
__device__ int   g_perm  [NPULSES];
__device__ int   g_bsum  [256];
__device__ int   g_is64;
__device__ float g_wt    [128 * 64];              // W transposed: [k][j]
__device__ float g_concat[(size_t)NDOMS * 128];   // [NDOMS][128] mean|max

// ---------------------------------------------------------------- idx dtype probe
__global__ void k_detect(const unsigned int* __restrict__ idx32) {
    int is64 = 1;
    for (int i = 0; i < 128; i++)
        if (idx32[2 * i + 1] != 0u) { is64 = 0; break; }
    g_is64 = is64;
}

__device__ __forceinline__ int load_idx(const void* __restrict__ idx, int i) {
    if (g_is64) return (int)((const long long*)idx)[i];
    return ((const int*)idx)[i];
}

// ---------------------------------------------------------------- zero counts
__global__ void k_zero() {
    int i = blockIdx.x * 1024 + threadIdx.x;
    g_count[i] = 0;
}

// ---------------------------------------------------------------- W transpose
__global__ void k_wt(const float* __restrict__ W) {
    int s = blockIdx.x * 256 + threadIdx.x;      // 8192 threads
    int j = s >> 7, k = s & 127;
    g_wt[k * 64 + j] = W[s];                     // W[j][k] -> g_wt[k][j]
}

// ---------------------------------------------------------------- histogram
__global__ void k_hist(const void* __restrict__ idx, int n) {
    int i = blockIdx.x * 256 + threadIdx.x;
    if (i < n) atomicAdd(&g_count[load_idx(idx, i)], 1);
}

// ---------------------------------------------------------------- scan (3 phases)
__global__ void k_scan1() {
    __shared__ int sh[1024];
    int t = threadIdx.x;
    int i = blockIdx.x * 1024 + t;
    int v = g_count[i];
    sh[t] = v;
    __syncthreads();
    for (int off = 1; off < 1024; off <<= 1) {
        int add = (t >= off) ? sh[t - off] : 0;
        __syncthreads();
        sh[t] += add;
        __syncthreads();
    }
    g_offset[i] = sh[t] - v;
    if (t == 1023) g_bsum[blockIdx.x] = sh[t];
}

__global__ void k_scan2() {
    __shared__ int sh[256];
    int t = threadIdx.x;
    int v = g_bsum[t];
    sh[t] = v;
    __syncthreads();
    for (int off = 1; off < 256; off <<= 1) {
        int add = (t >= off) ? sh[t - off] : 0;
        __syncthreads();
        sh[t] += add;
        __syncthreads();
    }
    g_bsum[t] = sh[t] - v;
}

__global__ void k_scan3() {
    int t = threadIdx.x;
    int i = blockIdx.x * 1024 + t;
    int o = g_offset[i] + g_bsum[blockIdx.x];
    g_offset[i] = o;
    g_cursor[i] = o;
}

// ---------------------------------------------------------------- scatter pulse ids
__global__ void k_scatter(const void* __restrict__ idx, int n) {
    int i = blockIdx.x * 256 + threadIdx.x;
    if (i < n) {
        int d   = load_idx(idx, i);
        int pos = atomicAdd(&g_cursor[d], 1);
        g_perm[pos] = i;
    }
}

// ---------------------------------------------------------------- pool: warp per DOM
// lane L owns dims {2L,2L+1}. Unroll x4: 4 independent 256B row loads in
// flight per warp (MLP=4) + pipelined perm-index preload.
__global__ void __launch_bounds__(256) k_pool(const float* __restrict__ emb) {
    int gw   = (blockIdx.x * blockDim.x + threadIdx.x) >> 5;
    int lane = threadIdx.x & 31;
    if (gw >= NDOMS) return;

    int start = g_offset[gw];
    int cnt   = g_count[gw];

    const float2* e2 = (const float2*)emb;
    float sx = 0.f, sy = 0.f;
    float mx = -FLT_MAX, my = -FLT_MAX;

    int i = 0;
    int p0, p1, p2, p3;
    if (cnt >= 4) {
        p0 = g_perm[start];     p1 = g_perm[start + 1];
        p2 = g_perm[start + 2]; p3 = g_perm[start + 3];
    }
    while (i + 4 <= cnt) {
        // issue all 4 row loads back-to-back (independent)
        float2 v0 = e2[(size_t)p0 * 32 + lane];
        float2 v1 = e2[(size_t)p1 * 32 + lane];
        float2 v2 = e2[(size_t)p2 * 32 + lane];
        float2 v3 = e2[(size_t)p3 * 32 + lane];
        i += 4;
        if (i + 4 <= cnt) {   // preload next indices while rows are in flight
            p0 = g_perm[start + i];     p1 = g_perm[start + i + 1];
            p2 = g_perm[start + i + 2]; p3 = g_perm[start + i + 3];
        }
        sx += (v0.x + v1.x) + (v2.x + v3.x);
        sy += (v0.y + v1.y) + (v2.y + v3.y);
        mx = fmaxf(mx, fmaxf(fmaxf(v0.x, v1.x), fmaxf(v2.x, v3.x)));
        my = fmaxf(my, fmaxf(fmaxf(v0.y, v1.y), fmaxf(v2.y, v3.y)));
    }
    for (; i < cnt; i++) {
        int p = g_perm[start + i];
        float2 v = e2[(size_t)p * 32 + lane];
        sx += v.x; sy += v.y;
        mx = fmaxf(mx, v.x); my = fmaxf(my, v.y);
    }

    float inv = 1.0f / (float)(cnt > 0 ? cnt : 1);
    if (cnt == 0) { mx = 0.f; my = 0.f; }

    float2* crow = (float2*)(g_concat + (size_t)gw * 128);
    crow[lane]      = make_float2(sx * inv, sy * inv);   // mean cols [0,64)
    crow[32 + lane] = make_float2(mx, my);               // max  cols [64,128)
}

// ---------------------------------------------------------------- projection GEMM
// persistent grid-stride: W tile loaded ONCE per block (was: per tile).
// C[262144,64] = A[262144,128] @ Wt(128,64) + bias
// 32 dom-rows/tile, 128 threads, 4x4 micro-tile; dyn smem 49152B.
#define GEMM_BLOCKS 592   // 148 SMs * 4 (smem-limited occupancy)

__global__ void __launch_bounds__(128) k_gemm(const float* __restrict__ bias,
                                              float* __restrict__ out) {
    extern __shared__ float sm[];
    float* As = sm;                 // [32][128]
    float* Bs = sm + 32 * 128;      // [128][64]

    int tid = threadIdx.x;

    // load pre-transposed W once per block
    const float4* Wt4 = (const float4*)g_wt;
    float4* Bs4 = (float4*)Bs;
    #pragma unroll
    for (int i = 0; i < 16; i++)
        Bs4[tid + i * 128] = Wt4[tid + i * 128];

    int tj = tid & 15, tm = tid >> 4;
    int m0 = tm * 4, j0 = tj * 4;
    float4 bv = *(const float4*)&bias[j0];

    float4* As4 = (float4*)As;

    for (int tile = blockIdx.x; tile < NDOMS / 32; tile += GEMM_BLOCKS) {
        __syncthreads();   // As consumers from previous tile done (also covers Bs once)
        const float4* A4 = (const float4*)(g_concat + (size_t)tile * 32 * 128);
        #pragma unroll
        for (int i = 0; i < 8; i++)
            As4[tid + i * 128] = A4[tid + i * 128];
        __syncthreads();

        float c[4][4];
        #pragma unroll
        for (int i = 0; i < 4; i++)
            #pragma unroll
            for (int j = 0; j < 4; j++) c[i][j] = 0.f;

        #pragma unroll 8
        for (int k = 0; k < 128; k++) {
            float a0 = As[(m0 + 0) * 128 + k];
            float a1 = As[(m0 + 1) * 128 + k];
            float a2 = As[(m0 + 2) * 128 + k];
            float a3 = As[(m0 + 3) * 128 + k];
            float4 bb = *(const float4*)&Bs[k * 64 + j0];
            c[0][0] = fmaf(a0, bb.x, c[0][0]); c[0][1] = fmaf(a0, bb.y, c[0][1]);
            c[0][2] = fmaf(a0, bb.z, c[0][2]); c[0][3] = fmaf(a0, bb.w, c[0][3]);
            c[1][0] = fmaf(a1, bb.x, c[1][0]); c[1][1] = fmaf(a1, bb.y, c[1][1]);
            c[1][2] = fmaf(a1, bb.z, c[1][2]); c[1][3] = fmaf(a1, bb.w, c[1][3]);
            c[2][0] = fmaf(a2, bb.x, c[2][0]); c[2][1] = fmaf(a2, bb.y, c[2][1]);
            c[2][2] = fmaf(a2, bb.z, c[2][2]); c[2][3] = fmaf(a2, bb.w, c[2][3]);
            c[3][0] = fmaf(a3, bb.x, c[3][0]); c[3][1] = fmaf(a3, bb.y, c[3][1]);
            c[3][2] = fmaf(a3, bb.z, c[3][2]); c[3][3] = fmaf(a3, bb.w, c[3][3]);
        }

        int dom0 = tile * 32;
        #pragma unroll
        for (int i = 0; i < 4; i++) {
            float4 r;
            r.x = c[i][0] + bv.x; r.y = c[i][1] + bv.y;
            r.z = c[i][2] + bv.z; r.w = c[i][3] + bv.w;
            *(float4*)&out[(size_t)(dom0 + m0 + i) * 64 + j0] = r;
        }
    }
}

// ---------------------------------------------------------------- launch
extern "C" void kernel_launch(void* const* d_in, const int* in_sizes, int n_in,
                              void* d_out, int out_size) {
    const float* emb = nullptr;
    const void*  idx = nullptr;
    const float* W   = nullptr;
    const float* b   = nullptr;
    for (int i = 0; i < n_in; i++) {
        long long sz = in_sizes[i];
        if (sz == 268435456LL || sz == 1073741824LL)           emb = (const float*)d_in[i];
        else if (sz == 4194304LL || sz == 33554432LL
                                 || sz == 16777216LL)          idx = d_in[i];
        else if (sz == 8192LL || sz == 32768LL)                W   = (const float*)d_in[i];
        else if (sz == 64LL  || sz == 256LL)                   b   = (const float*)d_in[i];
    }
    if (!emb || !idx || !W || !b) {
        emb = (const float*)d_in[0];
        idx = d_in[1];
        if (n_in >= 5) { W = (const float*)d_in[3]; b = (const float*)d_in[4]; }
        else           { W = (const float*)d_in[2]; b = (const float*)d_in[3]; }
    }
    float* out = (float*)d_out;
    const int n = NPULSES;

    k_detect <<<1, 1>>>((const unsigned int*)idx);
    k_zero   <<<NDOMS / 1024, 1024>>>();
    k_wt     <<<32, 256>>>(W);
    k_hist   <<<(n + 255) / 256, 256>>>(idx, n);
    k_scan1  <<<256, 1024>>>();
    k_scan2  <<<1, 256>>>();
    k_scan3  <<<256, 1024>>>();
    k_scatter<<<(n + 255) / 256, 256>>>(idx, n);
    k_pool   <<<NDOMS / 8, 256>>>(emb);
    k_gemm   <<<GEMM_BLOCKS, 128, 49152>>>(b, out);
}

// round 5
// speedup vs baseline: 1.0734x; 1.0092x over previous
#include <cuda_runtime.h>
#include <cstdint>
#include <cfloat>

#define NDOMS   262144
#define NPULSES 4194304
#define EMBED   64

// ---- static scratch (no allocs allowed) ----
__device__ int   g_count [NDOMS];
__device__ int   g_offset[NDOMS];
__device__ int   g_cursor[NDOMS];
__device__ int   g_perm  [NPULSES];
__device__ int   g_bsum  [256];
__device__ int   g_is64;
__device__ float g_wt    [128 * 64];              // W transposed: [k][j]
__device__ float g_concat[(size_t)NDOMS * 128];   // [NDOMS][128] mean|max

// ---- f32x2 packed helpers ----
__device__ __forceinline__ unsigned long long pack2(float x, float y) {
    unsigned long long u;
    asm("mov.b64 %0, {%1, %2};" : "=l"(u) : "f"(x), "f"(y));
    return u;
}
__device__ __forceinline__ void unpack2(unsigned long long u, float& x, float& y) {
    asm("mov.b64 {%0, %1}, %2;" : "=f"(x), "=f"(y) : "l"(u));
}
__device__ __forceinline__ void ffma2(unsigned long long& acc,
                                      unsigned long long a, unsigned long long b) {
    asm("fma.rn.f32x2 %0, %1, %2, %0;" : "+l"(acc) : "l"(a), "l"(b));
}

// ---------------------------------------------------------------- idx dtype probe
__global__ void k_detect(const unsigned int* __restrict__ idx32) {
    int is64 = 1;
    for (int i = 0; i < 128; i++)
        if (idx32[2 * i + 1] != 0u) { is64 = 0; break; }
    g_is64 = is64;
}

__device__ __forceinline__ int load_idx(const void* __restrict__ idx, int i) {
    if (g_is64) return (int)((const long long*)idx)[i];
    return ((const int*)idx)[i];
}

// ---------------------------------------------------------------- zero counts
__global__ void k_zero() {
    int i = blockIdx.x * 1024 + threadIdx.x;
    g_count[i] = 0;
}

// ---------------------------------------------------------------- W transpose
__global__ void k_wt(const float* __restrict__ W) {
    int s = blockIdx.x * 256 + threadIdx.x;      // 8192 threads
    int j = s >> 7, k = s & 127;
    g_wt[k * 64 + j] = W[s];                     // W[j][k] -> g_wt[k][j]
}

// ---------------------------------------------------------------- histogram
__global__ void k_hist(const void* __restrict__ idx, int n) {
    int i = blockIdx.x * 256 + threadIdx.x;
    if (i < n) atomicAdd(&g_count[load_idx(idx, i)], 1);
}

// ---------------------------------------------------------------- scan (3 phases)
__global__ void k_scan1() {
    __shared__ int sh[1024];
    int t = threadIdx.x;
    int i = blockIdx.x * 1024 + t;
    int v = g_count[i];
    sh[t] = v;
    __syncthreads();
    for (int off = 1; off < 1024; off <<= 1) {
        int add = (t >= off) ? sh[t - off] : 0;
        __syncthreads();
        sh[t] += add;
        __syncthreads();
    }
    g_offset[i] = sh[t] - v;
    if (t == 1023) g_bsum[blockIdx.x] = sh[t];
}

__global__ void k_scan2() {
    __shared__ int sh[256];
    int t = threadIdx.x;
    int v = g_bsum[t];
    sh[t] = v;
    __syncthreads();
    for (int off = 1; off < 256; off <<= 1) {
        int add = (t >= off) ? sh[t - off] : 0;
        __syncthreads();
        sh[t] += add;
        __syncthreads();
    }
    g_bsum[t] = sh[t] - v;
}

__global__ void k_scan3() {
    int t = threadIdx.x;
    int i = blockIdx.x * 1024 + t;
    int o = g_offset[i] + g_bsum[blockIdx.x];
    g_offset[i] = o;
    g_cursor[i] = o;
}

// ---------------------------------------------------------------- scatter pulse ids
__global__ void k_scatter(const void* __restrict__ idx, int n) {
    int i = blockIdx.x * 256 + threadIdx.x;
    if (i < n) {
        int d   = load_idx(idx, i);
        int pos = atomicAdd(&g_cursor[d], 1);
        g_perm[pos] = i;
    }
}

// ---------------------------------------------------------------- pool: warp per DOM
// lane L owns dims {2L,2L+1}. Unroll x8: 8 independent 256B row loads in
// flight per warp (MLP=8, M_max=55 headroom) + pipelined index preload.
__global__ void __launch_bounds__(256) k_pool(const float* __restrict__ emb) {
    int gw   = (blockIdx.x * blockDim.x + threadIdx.x) >> 5;
    int lane = threadIdx.x & 31;
    if (gw >= NDOMS) return;

    int start = g_offset[gw];
    int cnt   = g_count[gw];

    const float2* e2 = (const float2*)emb;
    float sx = 0.f, sy = 0.f;
    float mx = -FLT_MAX, my = -FLT_MAX;

    int i = 0;
    int p[8];
    if (cnt >= 8) {
        #pragma unroll
        for (int u = 0; u < 8; u++) p[u] = g_perm[start + u];
    }
    while (i + 8 <= cnt) {
        float2 v[8];
        #pragma unroll
        for (int u = 0; u < 8; u++)                 // 8 loads issued back-to-back
            v[u] = e2[(size_t)p[u] * 32 + lane];
        i += 8;
        if (i + 8 <= cnt) {
            #pragma unroll
            for (int u = 0; u < 8; u++) p[u] = g_perm[start + i + u];
        }
        #pragma unroll
        for (int u = 0; u < 8; u++) {
            sx += v[u].x; sy += v[u].y;
            mx = fmaxf(mx, v[u].x); my = fmaxf(my, v[u].y);
        }
    }
    for (; i < cnt; i++) {
        int q = g_perm[start + i];
        float2 v = e2[(size_t)q * 32 + lane];
        sx += v.x; sy += v.y;
        mx = fmaxf(mx, v.x); my = fmaxf(my, v.y);
    }

    float inv = 1.0f / (float)(cnt > 0 ? cnt : 1);
    if (cnt == 0) { mx = 0.f; my = 0.f; }

    float2* crow = (float2*)(g_concat + (size_t)gw * 128);
    crow[lane]      = make_float2(sx * inv, sy * inv);   // mean cols [0,64)
    crow[32 + lane] = make_float2(mx, my);               // max  cols [64,128)
}

// ---------------------------------------------------------------- projection GEMM
// persistent; FFMA2 (fma.rn.f32x2) inner loop, k-vectorized A fragments.
// C[262144,64] = A[262144,128] @ Wt(128,64) + bias
// 32 dom-rows/tile, 128 threads, 4m x 4j (= 4m x 2 f32x2) per thread.
#define GEMM_BLOCKS 592   // 148 SMs * 4 (smem-limited occupancy)

__global__ void __launch_bounds__(128) k_gemm(const float* __restrict__ bias,
                                              float* __restrict__ out) {
    extern __shared__ float sm[];
    float* As = sm;                 // [32][128]
    float* Bs = sm + 32 * 128;      // [128][64]

    int tid = threadIdx.x;

    // load pre-transposed W once per block
    const float4* Wt4 = (const float4*)g_wt;
    float4* Bs4 = (float4*)Bs;
    #pragma unroll
    for (int i = 0; i < 16; i++)
        Bs4[tid + i * 128] = Wt4[tid + i * 128];

    int tj = tid & 15, tm = tid >> 4;
    int m0 = tm * 4, j0 = tj * 4;
    float4 bv4 = *(const float4*)&bias[j0];

    float4* As4 = (float4*)As;
    const unsigned long long* Bsu = (const unsigned long long*)Bs;   // [128][32]

    for (int tile = blockIdx.x; tile < NDOMS / 32; tile += GEMM_BLOCKS) {
        __syncthreads();   // previous tile consumers done (also covers Bs once)
        const float4* A4 = (const float4*)(g_concat + (size_t)tile * 32 * 128);
        #pragma unroll
        for (int i = 0; i < 8; i++)
            As4[tid + i * 128] = A4[tid + i * 128];
        __syncthreads();

        unsigned long long acc[4][2];
        #pragma unroll
        for (int i = 0; i < 4; i++) { acc[i][0] = 0ULL; acc[i][1] = 0ULL; }

        #pragma unroll 4
        for (int kk = 0; kk < 128; kk += 4) {
            // a fragments: 4 k-values per m-row in one LDS.128
            float4 a0 = *(const float4*)&As[(m0 + 0) * 128 + kk];
            float4 a1 = *(const float4*)&As[(m0 + 1) * 128 + kk];
            float4 a2 = *(const float4*)&As[(m0 + 2) * 128 + kk];
            float4 a3 = *(const float4*)&As[(m0 + 3) * 128 + kk];
            const float* af0 = (const float*)&a0;
            const float* af1 = (const float*)&a1;
            const float* af2 = (const float*)&a2;
            const float* af3 = (const float*)&a3;
            #pragma unroll
            for (int dk = 0; dk < 4; dk++) {
                int k = kk + dk;
                unsigned long long b01 = Bsu[k * 32 + 2 * tj];
                unsigned long long b23 = Bsu[k * 32 + 2 * tj + 1];
                unsigned long long aa;
                aa = pack2(af0[dk], af0[dk]); ffma2(acc[0][0], aa, b01); ffma2(acc[0][1], aa, b23);
                aa = pack2(af1[dk], af1[dk]); ffma2(acc[1][0], aa, b01); ffma2(acc[1][1], aa, b23);
                aa = pack2(af2[dk], af2[dk]); ffma2(acc[2][0], aa, b01); ffma2(acc[2][1], aa, b23);
                aa = pack2(af3[dk], af3[dk]); ffma2(acc[3][0], aa, b01); ffma2(acc[3][1], aa, b23);
            }
        }

        int dom0 = tile * 32;
        #pragma unroll
        for (int i = 0; i < 4; i++) {
            float c0, c1, c2, c3;
            unpack2(acc[i][0], c0, c1);
            unpack2(acc[i][1], c2, c3);
            float4 r;
            r.x = c0 + bv4.x; r.y = c1 + bv4.y;
            r.z = c2 + bv4.z; r.w = c3 + bv4.w;
            *(float4*)&out[(size_t)(dom0 + m0 + i) * 64 + j0] = r;
        }
    }
}

// ---------------------------------------------------------------- launch
extern "C" void kernel_launch(void* const* d_in, const int* in_sizes, int n_in,
                              void* d_out, int out_size) {
    const float* emb = nullptr;
    const void*  idx = nullptr;
    const float* W   = nullptr;
    const float* b   = nullptr;
    for (int i = 0; i < n_in; i++) {
        long long sz = in_sizes[i];
        if (sz == 268435456LL || sz == 1073741824LL)           emb = (const float*)d_in[i];
        else if (sz == 4194304LL || sz == 33554432LL
                                 || sz == 16777216LL)          idx = d_in[i];
        else if (sz == 8192LL || sz == 32768LL)                W   = (const float*)d_in[i];
        else if (sz == 64LL  || sz == 256LL)                   b   = (const float*)d_in[i];
    }
    if (!emb || !idx || !W || !b) {
        emb = (const float*)d_in[0];
        idx = d_in[1];
        if (n_in >= 5) { W = (const float*)d_in[3]; b = (const float*)d_in[4]; }
        else           { W = (const float*)d_in[2]; b = (const float*)d_in[3]; }
    }
    float* out = (float*)d_out;
    const int n = NPULSES;

    k_detect <<<1, 1>>>((const unsigned int*)idx);
    k_zero   <<<NDOMS / 1024, 1024>>>();
    k_wt     <<<32, 256>>>(W);
    k_hist   <<<(n + 255) / 256, 256>>>(idx, n);
    k_scan1  <<<256, 1024>>>();
    k_scan2  <<<1, 256>>>();
    k_scan3  <<<256, 1024>>>();
    k_scatter<<<(n + 255) / 256, 256>>>(idx, n);
    k_pool   <<<NDOMS / 8, 256>>>(emb);
    k_gemm   <<<GEMM_BLOCKS, 128, 49152>>>(b, out);
}